// round 8
// baseline (speedup 1.0000x reference)
#include <cuda_runtime.h>

// R8 = R7 resubmitted unchanged: R7 bench died on container infra (twice),
// kernel never executed. No evidence to update on.

#define L_NODES 30000
#define JDIM 64
#define NFEAT 16

// Scratch (allocation-free): per-node tables.
__device__ float g_hXWt[L_NODES * JDIM];
__device__ float g_hXWb[L_NODES * JDIM];

typedef unsigned long long u64;

// ---- packed f32x2 helpers (sm_100+) ----------------------------------------
__device__ __forceinline__ u64 pack2(float lo, float hi) {
    u64 r; asm("mov.b64 %0, {%1, %2};" : "=l"(r) : "f"(lo), "f"(hi)); return r;
}
__device__ __forceinline__ void ffma2(u64& d, u64 a, u64 b) {
    asm("fma.rn.f32x2 %0, %1, %2, %0;" : "+l"(d) : "l"(a), "l"(b));
}
__device__ __forceinline__ float hsum2(u64 v) {
    float lo, hi; asm("mov.b64 {%0, %1}, %2;" : "=f"(lo), "=f"(hi) : "l"(v));
    return lo + hi;
}

// ---------------------------------------------------------------------------
// Prep: hx = relu(X@h1_w+h1_b);  hXWt = hx@Wt;  hXWb = hx@Wb.
// k-split layout: node group = 64 threads = 2 warps. Warp w owns cols
// [32w,32w+32); lane s: cols c0=32w+2*(s&15), c0+1; k-half h=s>>4.
// Each thread reads only 32 hx floats per matvec; halves combined via
// shfl.xor(16). Weights (2 cols x 2 mats x 32 k) packed in 64 b64 regs.
// ---------------------------------------------------------------------------
__global__ __launch_bounds__(256) void prep_kernel(
    const float* __restrict__ X,
    const float* __restrict__ h1w,
    const float* __restrict__ h1b,
    const float* __restrict__ g1w)
{
    __shared__ __align__(16) float s_hx[4][64];

    int tid = threadIdx.x;
    int g   = tid >> 6;            // node-lane in block (4 nodes/block)
    int j   = tid & 63;            // column this thread computes hx for
    int w   = (tid >> 5) & 1;      // warp within node group
    int s   = tid & 31;            // lane
    int h   = s >> 4;              // k-half
    int c0  = w * 32 + 2 * (s & 15);

    // hx weights: col j
    float wh[16];
#pragma unroll
    for (int k = 0; k < 16; k++) wh[k] = h1w[k * 64 + j];
    float bj = h1b[j];

    // matvec weights: Wt/Wb at cols {c0,c0+1}, k in [32h, 32h+32), packed pairs
    u64 wt2[32], wb2[32];   // [k2*2 + c]
#pragma unroll
    for (int k2 = 0; k2 < 16; k2++) {
#pragma unroll
        for (int c = 0; c < 2; c++) {
            int kk = 32 * h + 2 * k2;
            wt2[k2 * 2 + c] = pack2(g1w[kk * 64 + c0 + c],
                                    g1w[(kk + 1) * 64 + c0 + c]);
            wb2[k2 * 2 + c] = pack2(g1w[(64 + kk) * 64 + c0 + c],
                                    g1w[(64 + kk + 1) * 64 + c0 + c]);
        }
    }

    const int NGROUPS = L_NODES / 4;   // 7500
    for (int grp = blockIdx.x; grp < NGROUPS; grp += gridDim.x) {
        int l = grp * 4 + g;

        // hx_j = relu(X[l] @ h1w[:,j] + b_j); X row is a broadcast load.
        const float4* xr = (const float4*)(X + l * NFEAT);
        float4 x0 = xr[0], x1 = xr[1], x2 = xr[2], x3 = xr[3];
        float acc = bj;
        acc = fmaf(x0.x, wh[ 0], acc); acc = fmaf(x0.y, wh[ 1], acc);
        acc = fmaf(x0.z, wh[ 2], acc); acc = fmaf(x0.w, wh[ 3], acc);
        acc = fmaf(x1.x, wh[ 4], acc); acc = fmaf(x1.y, wh[ 5], acc);
        acc = fmaf(x1.z, wh[ 6], acc); acc = fmaf(x1.w, wh[ 7], acc);
        acc = fmaf(x2.x, wh[ 8], acc); acc = fmaf(x2.y, wh[ 9], acc);
        acc = fmaf(x2.z, wh[10], acc); acc = fmaf(x2.w, wh[11], acc);
        acc = fmaf(x3.x, wh[12], acc); acc = fmaf(x3.y, wh[13], acc);
        acc = fmaf(x3.z, wh[14], acc); acc = fmaf(x3.w, wh[15], acc);
        s_hx[g][j] = fmaxf(acc, 0.0f);
        __syncthreads();

        // half-dot over this thread's k-half for 2 cols x 2 mats
        u64 at0 = 0ull, at1 = 0ull, ab0 = 0ull, ab1 = 0ull;
        const u64* vp = (const u64*)s_hx[g];   // (hx_2k, hx_2k+1) pairs
#pragma unroll
        for (int k2 = 0; k2 < 16; k2++) {
            u64 v = vp[h * 16 + k2];
            ffma2(at0, wt2[k2 * 2 + 0], v);
            ffma2(at1, wt2[k2 * 2 + 1], v);
            ffma2(ab0, wb2[k2 * 2 + 0], v);
            ffma2(ab1, wb2[k2 * 2 + 1], v);
        }
        float t0 = hsum2(at0), t1 = hsum2(at1);
        float b0 = hsum2(ab0), b1 = hsum2(ab1);
        t0 += __shfl_xor_sync(0xffffffffu, t0, 16);
        t1 += __shfl_xor_sync(0xffffffffu, t1, 16);
        b0 += __shfl_xor_sync(0xffffffffu, b0, 16);
        b1 += __shfl_xor_sync(0xffffffffu, b1, 16);
        if (h == 0) {
            g_hXWt[l * 64 + c0]     = t0;
            g_hXWt[l * 64 + c0 + 1] = t1;
            g_hXWb[l * 64 + c0]     = b0;
            g_hXWb[l * 64 + c0 + 1] = b1;
        }
        __syncthreads();   // s_hx reused next iteration
    }
}

// ---------------------------------------------------------------------------
// Main: 1 warp per node. k-split: lane t -> 4 cols c=4q..4q+3 (q=t&15),
// k-half h=t>>4. Per matvec each thread reads 16 LDS.64 (half the vector),
// does 64 FFMA2 across 4 independent chains, combines halves with 4 shfl.
// Wb slice (4 cols x 32 k) packed in 64 b64 regs.
// ---------------------------------------------------------------------------
__global__ __launch_bounds__(256) void ggcn_main_kernel(
    const int*   __restrict__ nbr,
    const float* __restrict__ g1w,
    const float* __restrict__ g1b,
    const float* __restrict__ fw,
    const float* __restrict__ fb,
    float*       __restrict__ out)
{
    __shared__ __align__(16) float s_v[8][6][64];   // per-warp staging, 12KB

    int warp = threadIdx.x >> 5;
    int t    = threadIdx.x & 31;
    int q    = t & 15;         // col group: cols 4q..4q+3
    int h    = t >> 4;         // k-half
    int l    = blockIdx.x * 8 + warp;

    // Wb[k][4q+c] for k in [32h, 32h+32), packed over k-pairs: wq[k2*4+c]
    u64 wq[64];
#pragma unroll
    for (int k2 = 0; k2 < 16; k2++) {
        int kk = 32 * h + 2 * k2;
#pragma unroll
        for (int c = 0; c < 4; c++) {
            wq[k2 * 4 + c] = pack2(g1w[(64 + kk) * 64 + 4 * q + c],
                                   g1w[(64 + kk + 1) * 64 + 4 * q + c]);
        }
    }
    float4 b4    = *(const float4*)(g1b + 4 * q);
    float  bb[4] = {b4.x, b4.y, b4.z, b4.w};

    int4 nb = ((const int4*)nbr)[l];
    int ni[4] = {nb.x, nb.y, nb.z, nb.w};
    float A[4][4], B[4][4];
#pragma unroll
    for (int i = 0; i < 4; i++) {
        float4 a = *(const float4*)(g_hXWt + ni[i] * 64 + 4 * q);
        float4 v = *(const float4*)(g_hXWb + ni[i] * 64 + 4 * q);
        A[i][0] = a.x; A[i][1] = a.y; A[i][2] = a.z; A[i][3] = a.w;
        B[i][0] = v.x; B[i][1] = v.y; B[i][2] = v.z; B[i][3] = v.w;
    }
    float4 hx4 = *(const float4*)(g_hXWt + l * 64 + 4 * q);
    float hxwt[4] = {hx4.x, hx4.y, hx4.z, hx4.w};

    // ---- pairs: stage 6 pairf vectors (h==0 lanes write; values identical) --
    const int PA[6] = {0, 0, 0, 1, 1, 2};
    const int PB[6] = {1, 2, 3, 2, 3, 3};
#pragma unroll
    for (int p = 0; p < 6; p++) {
        int i0 = PA[p], i1 = PB[p];
        float4 v;
        v.x = 0.5f * (fmaxf(A[i0][0] + B[i1][0] + bb[0], 0.0f) +
                      fmaxf(A[i1][0] + B[i0][0] + bb[0], 0.0f));
        v.y = 0.5f * (fmaxf(A[i0][1] + B[i1][1] + bb[1], 0.0f) +
                      fmaxf(A[i1][1] + B[i0][1] + bb[1], 0.0f));
        v.z = 0.5f * (fmaxf(A[i0][2] + B[i1][2] + bb[2], 0.0f) +
                      fmaxf(A[i1][2] + B[i0][2] + bb[2], 0.0f));
        v.w = 0.5f * (fmaxf(A[i0][3] + B[i1][3] + bb[3], 0.0f) +
                      fmaxf(A[i1][3] + B[i0][3] + bb[3], 0.0f));
        if (h == 0) ((float4*)s_v[warp][p])[q] = v;
    }
    __syncwarp();

    // ---- PWb = pairf @ Wb : 6 matvecs, 2 at a time, k-split + shfl ----
    float PWb[6][4];
#pragma unroll
    for (int p = 0; p < 6; p += 2) {
        u64 a0[4] = {0ull, 0ull, 0ull, 0ull};
        u64 a1[4] = {0ull, 0ull, 0ull, 0ull};
        const u64* v0 = (const u64*)s_v[warp][p];
        const u64* v1 = (const u64*)s_v[warp][p + 1];
#pragma unroll
        for (int k2 = 0; k2 < 16; k2++) {
            u64 v = v0[h * 16 + k2];
            u64 u = v1[h * 16 + k2];
#pragma unroll
            for (int c = 0; c < 4; c++) {
                ffma2(a0[c], wq[k2 * 4 + c], v);
                ffma2(a1[c], wq[k2 * 4 + c], u);
            }
        }
#pragma unroll
        for (int c = 0; c < 4; c++) {
            float s0 = hsum2(a0[c]);
            float s1 = hsum2(a1[c]);
            s0 += __shfl_xor_sync(0xffffffffu, s0, 16);
            s1 += __shfl_xor_sync(0xffffffffu, s1, 16);
            PWb[p][c] = s0;
            PWb[p + 1][c] = s1;
        }
    }
    __syncwarp();   // s_v about to be overwritten

    // ---- triples (indexed by missing element m) ----
    const int PIDX[4][4] = {{-1, 0, 1, 2},
                            { 0,-1, 3, 4},
                            { 1, 3,-1, 5},
                            { 2, 4, 5,-1}};
#pragma unroll
    for (int m = 0; m < 4; m++) {
        float acc[4] = {0.f, 0.f, 0.f, 0.f};
#pragma unroll
        for (int i = 0; i < 4; i++) {
            if (i == m) continue;
            int a = -1, cc = -1;
#pragma unroll
            for (int z = 0; z < 4; z++) {
                if (z != m && z != i) { if (a < 0) a = z; else cc = z; }
            }
            int pi = PIDX[a][cc];
#pragma unroll
            for (int c = 0; c < 4; c++)
                acc[c] += fmaxf(A[i][c] + PWb[pi][c] + bb[c], 0.0f);
        }
        if (h == 0) {
            float4 v = {acc[0] * (1.0f / 3.0f), acc[1] * (1.0f / 3.0f),
                        acc[2] * (1.0f / 3.0f), acc[3] * (1.0f / 3.0f)};
            ((float4*)s_v[warp][m])[q] = v;
        }
    }
    __syncwarp();

    // ---- TWb = triplef @ Wb : 4 matvecs, 2 at a time ----
    float TWb[4][4];
#pragma unroll
    for (int m = 0; m < 4; m += 2) {
        u64 a0[4] = {0ull, 0ull, 0ull, 0ull};
        u64 a1[4] = {0ull, 0ull, 0ull, 0ull};
        const u64* v0 = (const u64*)s_v[warp][m];
        const u64* v1 = (const u64*)s_v[warp][m + 1];
#pragma unroll
        for (int k2 = 0; k2 < 16; k2++) {
            u64 v = v0[h * 16 + k2];
            u64 u = v1[h * 16 + k2];
#pragma unroll
            for (int c = 0; c < 4; c++) {
                ffma2(a0[c], wq[k2 * 4 + c], v);
                ffma2(a1[c], wq[k2 * 4 + c], u);
            }
        }
#pragma unroll
        for (int c = 0; c < 4; c++) {
            float s0 = hsum2(a0[c]);
            float s1 = hsum2(a1[c]);
            s0 += __shfl_xor_sync(0xffffffffu, s0, 16);
            s1 += __shfl_xor_sync(0xffffffffu, s1, 16);
            TWb[m][c] = s0;
            TWb[m + 1][c] = s1;
        }
    }
    __syncwarp();   // s_v reused for E

    // ---- quad + E ----
    {
        float qv[4] = {0.f, 0.f, 0.f, 0.f};
#pragma unroll
        for (int i = 0; i < 4; i++)
#pragma unroll
            for (int c = 0; c < 4; c++)
                qv[c] += fmaxf(A[i][c] + TWb[i][c] + bb[c], 0.0f);
        if (h == 0) {
            float4 v = {fmaxf(qv[0] * 0.25f, 0.0f), fmaxf(qv[1] * 0.25f, 0.0f),
                        fmaxf(qv[2] * 0.25f, 0.0f), fmaxf(qv[3] * 0.25f, 0.0f)};
            ((float4*)s_v[warp][0])[q] = v;
        }
    }
    __syncwarp();

    // ---- E2 = relu(hxwt + E@Wb + b) ----
    float E2[4];
    {
        u64 a0[4] = {0ull, 0ull, 0ull, 0ull};
        const u64* v0 = (const u64*)s_v[warp][0];
#pragma unroll
        for (int k2 = 0; k2 < 16; k2++) {
            u64 v = v0[h * 16 + k2];
#pragma unroll
            for (int c = 0; c < 4; c++)
                ffma2(a0[c], wq[k2 * 4 + c], v);
        }
#pragma unroll
        for (int c = 0; c < 4; c++) {
            float s0 = hsum2(a0[c]);
            s0 += __shfl_xor_sync(0xffffffffu, s0, 16);
            E2[c] = fmaxf(hxwt[c] + s0 + bb[c], 0.0f);
        }
    }

    // ---- readout head: y = E2 @ final_w + final_b ----
    // h==1 lanes hold duplicate E2; zero them so the butterfly sums once.
    float p0 = 0.f, p1 = 0.f;
    if (h == 0) {
#pragma unroll
        for (int c = 0; c < 4; c++) {
            float2 f = *(const float2*)(fw + (4 * q + c) * 2);
            p0 = fmaf(E2[c], f.x, p0);
            p1 = fmaf(E2[c], f.y, p1);
        }
    }
#pragma unroll
    for (int off = 16; off > 0; off >>= 1) {
        p0 += __shfl_xor_sync(0xffffffffu, p0, off);
        p1 += __shfl_xor_sync(0xffffffffu, p1, off);
    }
    if (t == 0) {
        float2 o = {p0 + fb[0], p1 + fb[1]};
        *(float2*)(out + l * 2) = o;
    }
}

// ---------------------------------------------------------------------------
// kernel_launch: graph-capturable, allocation-free.
// Inputs: X, neighbors, h1_w, h1_b, g1_w, g1_b, final_w, final_b
// ---------------------------------------------------------------------------
extern "C" void kernel_launch(void* const* d_in, const int* in_sizes, int n_in,
                              void* d_out, int out_size)
{
    const float* X    = (const float*)d_in[0];
    const int*   nbr  = (const int*)  d_in[1];
    const float* h1w  = (const float*)d_in[2];
    const float* h1b  = (const float*)d_in[3];
    const float* g1w  = (const float*)d_in[4];
    const float* g1b  = (const float*)d_in[5];
    const float* fw   = (const float*)d_in[6];
    const float* fb   = (const float*)d_in[7];
    float* out = (float*)d_out;

    (void)in_sizes; (void)n_in; (void)out_size;

    prep_kernel<<<592, 256>>>(X, h1w, h1b, g1w);
    ggcn_main_kernel<<<L_NODES / 8, 256>>>(nbr, g1w, g1b, fw, fb, out);
}

// round 10
// speedup vs baseline: 1.5920x; 1.5920x over previous
#include <cuda_runtime.h>

// R10 = R9 resubmitted unchanged: R9 bench died on container infra (twice),
// kernel never executed. No evidence to update on.

#define L_NODES 30000
#define JDIM 64
#define NFEAT 16

// Scratch (allocation-free): per-node tables.
__device__ float g_hXWt[L_NODES * JDIM];
__device__ float g_hXWb[L_NODES * JDIM];

typedef unsigned long long u64;

// ---- packed f32x2 helpers (sm_100+) ----------------------------------------
__device__ __forceinline__ u64 pack2(float lo, float hi) {
    u64 r; asm("mov.b64 %0, {%1, %2};" : "=l"(r) : "f"(lo), "f"(hi)); return r;
}
__device__ __forceinline__ void ffma2(u64& d, u64 a, u64 b) {
    asm("fma.rn.f32x2 %0, %1, %2, %0;" : "+l"(d) : "l"(a), "l"(b));
}
__device__ __forceinline__ float hsum2(u64 v) {
    float lo, hi; asm("mov.b64 {%0, %1}, %2;" : "=f"(lo), "=f"(hi) : "l"(v));
    return lo + hi;
}

// ---------------------------------------------------------------------------
// Prep (R4/R6-measured ~23us): hx = relu(X@h1_w+h1_b); hXWt=hx@Wt; hXWb=hx@Wb.
// Weights in registers, persistent blocks. Unchanged from R6.
// ---------------------------------------------------------------------------
__global__ __launch_bounds__(256, 1) void prep_kernel(
    const float* __restrict__ X,
    const float* __restrict__ h1w,
    const float* __restrict__ h1b,
    const float* __restrict__ g1w)
{
    __shared__ __align__(16) float s_hx[4][64];

    int tid = threadIdx.x;
    int g = tid >> 6;
    int j = tid & 63;

    float wh[16], wt[64], wb[64];
#pragma unroll
    for (int k = 0; k < 16; k++) wh[k] = h1w[k * 64 + j];
#pragma unroll
    for (int k = 0; k < 64; k++) {
        wt[k] = g1w[k * 64 + j];
        wb[k] = g1w[(64 + k) * 64 + j];
    }
    float bj = h1b[j];

    const int NGROUPS = L_NODES / 4;   // 7500
    for (int grp = blockIdx.x; grp < NGROUPS; grp += gridDim.x) {
        int l = grp * 4 + g;

        const float4* xr = (const float4*)(X + l * NFEAT);
        float4 x0 = xr[0], x1 = xr[1], x2 = xr[2], x3 = xr[3];
        float acc = bj;
        acc = fmaf(x0.x, wh[ 0], acc); acc = fmaf(x0.y, wh[ 1], acc);
        acc = fmaf(x0.z, wh[ 2], acc); acc = fmaf(x0.w, wh[ 3], acc);
        acc = fmaf(x1.x, wh[ 4], acc); acc = fmaf(x1.y, wh[ 5], acc);
        acc = fmaf(x1.z, wh[ 6], acc); acc = fmaf(x1.w, wh[ 7], acc);
        acc = fmaf(x2.x, wh[ 8], acc); acc = fmaf(x2.y, wh[ 9], acc);
        acc = fmaf(x2.z, wh[10], acc); acc = fmaf(x2.w, wh[11], acc);
        acc = fmaf(x3.x, wh[12], acc); acc = fmaf(x3.y, wh[13], acc);
        acc = fmaf(x3.z, wh[14], acc); acc = fmaf(x3.w, wh[15], acc);
        s_hx[g][j] = fmaxf(acc, 0.0f);
        __syncthreads();

        float at = 0.0f, ab = 0.0f;
        const float4* vp = (const float4*)s_hx[g];
#pragma unroll
        for (int k4 = 0; k4 < 16; k4++) {
            float4 v = vp[k4];
            int r = 4 * k4;
            at = fmaf(v.x, wt[r + 0], at);  ab = fmaf(v.x, wb[r + 0], ab);
            at = fmaf(v.y, wt[r + 1], at);  ab = fmaf(v.y, wb[r + 1], ab);
            at = fmaf(v.z, wt[r + 2], at);  ab = fmaf(v.z, wb[r + 2], ab);
            at = fmaf(v.w, wt[r + 3], at);  ab = fmaf(v.w, wb[r + 3], ab);
        }
        g_hXWt[l * 64 + j] = at;
        g_hXWb[l * 64 + j] = ab;
        __syncthreads();
    }
}

// ---------------------------------------------------------------------------
// Main: R6 structure (1-warp matvecs at the crossbar phase floor: pure LDS.64
// broadcasts, no k-split, no mid-matvec shfl) but TWO NODES PER WARP.
// The 128 weight regs are node-invariant and amortize across both nodes;
// per loop iteration: 4 independent LDS streams + 8 independent FFMA2 chains
// doubles latency tolerance at occ=8 warps/SM.
// Thread t owns output columns t and t+32 for both nodes.
// ---------------------------------------------------------------------------
__global__ __launch_bounds__(256, 1) void ggcn_main_kernel(
    const int*   __restrict__ nbr,
    const float* __restrict__ g1w,
    const float* __restrict__ g1b,
    const float* __restrict__ fw,
    const float* __restrict__ fb,
    float*       __restrict__ out)
{
    __shared__ __align__(16) float s_v[8][2][6][64];   // [warp][node][vec][j]

    int warp = threadIdx.x >> 5;
    int t    = threadIdx.x & 31;
    int l0   = blockIdx.x * 16 + warp * 2;
    int l1   = l0 + 1;

    // Wb columns t, t+32 packed over k-pairs (shared by both nodes).
    u64 wlo[32], whi[32];
#pragma unroll
    for (int k2 = 0; k2 < 32; k2++) {
        wlo[k2] = pack2(g1w[(64 + 2 * k2) * 64 + t],
                        g1w[(64 + 2 * k2 + 1) * 64 + t]);
        whi[k2] = pack2(g1w[(64 + 2 * k2) * 64 + t + 32],
                        g1w[(64 + 2 * k2 + 1) * 64 + t + 32]);
    }
    float blo = g1b[t], bhi = g1b[t + 32];

    int4 nbA = ((const int4*)nbr)[l0];
    int4 nbB = ((const int4*)nbr)[l1];
    int niA[4] = {nbA.x, nbA.y, nbA.z, nbA.w};
    int niB[4] = {nbB.x, nbB.y, nbB.z, nbB.w};

    float A0l[4], A0h[4], A1l[4], A1h[4];
#pragma unroll
    for (int i = 0; i < 4; i++) {
        A0l[i] = g_hXWt[niA[i] * 64 + t];
        A0h[i] = g_hXWt[niA[i] * 64 + t + 32];
        A1l[i] = g_hXWt[niB[i] * 64 + t];
        A1h[i] = g_hXWt[niB[i] * 64 + t + 32];
    }
    float hx0l = g_hXWt[l0 * 64 + t], hx0h = g_hXWt[l0 * 64 + t + 32];
    float hx1l = g_hXWt[l1 * 64 + t], hx1h = g_hXWt[l1 * 64 + t + 32];

    // ---- pairs (B values scoped here so their registers die early) ----
    const int PA[6] = {0, 0, 0, 1, 1, 2};
    const int PB[6] = {1, 2, 3, 2, 3, 3};
    {
        float B0l[4], B0h[4], B1l[4], B1h[4];
#pragma unroll
        for (int i = 0; i < 4; i++) {
            B0l[i] = g_hXWb[niA[i] * 64 + t];
            B0h[i] = g_hXWb[niA[i] * 64 + t + 32];
            B1l[i] = g_hXWb[niB[i] * 64 + t];
            B1h[i] = g_hXWb[niB[i] * 64 + t + 32];
        }
#pragma unroll
        for (int p = 0; p < 6; p++) {
            int i0 = PA[p], i1 = PB[p];
            s_v[warp][0][p][t] =
                0.5f * (fmaxf(A0l[i0] + B0l[i1] + blo, 0.0f) +
                        fmaxf(A0l[i1] + B0l[i0] + blo, 0.0f));
            s_v[warp][0][p][t + 32] =
                0.5f * (fmaxf(A0h[i0] + B0h[i1] + bhi, 0.0f) +
                        fmaxf(A0h[i1] + B0h[i0] + bhi, 0.0f));
            s_v[warp][1][p][t] =
                0.5f * (fmaxf(A1l[i0] + B1l[i1] + blo, 0.0f) +
                        fmaxf(A1l[i1] + B1l[i0] + blo, 0.0f));
            s_v[warp][1][p][t + 32] =
                0.5f * (fmaxf(A1h[i0] + B1h[i1] + bhi, 0.0f) +
                        fmaxf(A1h[i1] + B1h[i0] + bhi, 0.0f));
        }
    }
    __syncwarp();

    // ---- PWb = pairf @ Wb : 6 matvecs x 2 nodes, 2 vecs at a time ----
    float PWb0l[6], PWb0h[6], PWb1l[6], PWb1h[6];
#pragma unroll
    for (int p = 0; p < 6; p += 2) {
        u64 a0l = 0ull, a0h = 0ull, a1l = 0ull, a1h = 0ull;   // node 0
        u64 c0l = 0ull, c0h = 0ull, c1l = 0ull, c1h = 0ull;   // node 1
        const u64* v0A = (const u64*)s_v[warp][0][p];
        const u64* v1A = (const u64*)s_v[warp][0][p + 1];
        const u64* v0B = (const u64*)s_v[warp][1][p];
        const u64* v1B = (const u64*)s_v[warp][1][p + 1];
#pragma unroll
        for (int k2 = 0; k2 < 32; k2++) {
            u64 vA = v0A[k2], uA = v1A[k2];
            u64 vB = v0B[k2], uB = v1B[k2];
            ffma2(a0l, wlo[k2], vA);  ffma2(a0h, whi[k2], vA);
            ffma2(a1l, wlo[k2], uA);  ffma2(a1h, whi[k2], uA);
            ffma2(c0l, wlo[k2], vB);  ffma2(c0h, whi[k2], vB);
            ffma2(c1l, wlo[k2], uB);  ffma2(c1h, whi[k2], uB);
        }
        PWb0l[p]     = hsum2(a0l);  PWb0h[p]     = hsum2(a0h);
        PWb0l[p + 1] = hsum2(a1l);  PWb0h[p + 1] = hsum2(a1h);
        PWb1l[p]     = hsum2(c0l);  PWb1h[p]     = hsum2(c0h);
        PWb1l[p + 1] = hsum2(c1l);  PWb1h[p + 1] = hsum2(c1h);
    }
    __syncwarp();   // s_v about to be overwritten

    // ---- triples (indexed by missing element m) ----
    const int PIDX[4][4] = {{-1, 0, 1, 2},
                            { 0,-1, 3, 4},
                            { 1, 3,-1, 5},
                            { 2, 4, 5,-1}};
#pragma unroll
    for (int m = 0; m < 4; m++) {
        float s0l = 0.f, s0h = 0.f, s1l = 0.f, s1h = 0.f;
#pragma unroll
        for (int i = 0; i < 4; i++) {
            if (i == m) continue;
            int a = -1, c = -1;
#pragma unroll
            for (int z = 0; z < 4; z++) {
                if (z != m && z != i) { if (a < 0) a = z; else c = z; }
            }
            int pi = PIDX[a][c];
            s0l += fmaxf(A0l[i] + PWb0l[pi] + blo, 0.0f);
            s0h += fmaxf(A0h[i] + PWb0h[pi] + bhi, 0.0f);
            s1l += fmaxf(A1l[i] + PWb1l[pi] + blo, 0.0f);
            s1h += fmaxf(A1h[i] + PWb1h[pi] + bhi, 0.0f);
        }
        s_v[warp][0][m][t]      = s0l * (1.0f / 3.0f);
        s_v[warp][0][m][t + 32] = s0h * (1.0f / 3.0f);
        s_v[warp][1][m][t]      = s1l * (1.0f / 3.0f);
        s_v[warp][1][m][t + 32] = s1h * (1.0f / 3.0f);
    }
    __syncwarp();

    // ---- TWb = triplef @ Wb : 4 matvecs x 2 nodes ----
    float TWb0l[4], TWb0h[4], TWb1l[4], TWb1h[4];
#pragma unroll
    for (int m = 0; m < 4; m += 2) {
        u64 a0l = 0ull, a0h = 0ull, a1l = 0ull, a1h = 0ull;
        u64 c0l = 0ull, c0h = 0ull, c1l = 0ull, c1h = 0ull;
        const u64* v0A = (const u64*)s_v[warp][0][m];
        const u64* v1A = (const u64*)s_v[warp][0][m + 1];
        const u64* v0B = (const u64*)s_v[warp][1][m];
        const u64* v1B = (const u64*)s_v[warp][1][m + 1];
#pragma unroll
        for (int k2 = 0; k2 < 32; k2++) {
            u64 vA = v0A[k2], uA = v1A[k2];
            u64 vB = v0B[k2], uB = v1B[k2];
            ffma2(a0l, wlo[k2], vA);  ffma2(a0h, whi[k2], vA);
            ffma2(a1l, wlo[k2], uA);  ffma2(a1h, whi[k2], uA);
            ffma2(c0l, wlo[k2], vB);  ffma2(c0h, whi[k2], vB);
            ffma2(c1l, wlo[k2], uB);  ffma2(c1h, whi[k2], uB);
        }
        TWb0l[m]     = hsum2(a0l);  TWb0h[m]     = hsum2(a0h);
        TWb0l[m + 1] = hsum2(a1l);  TWb0h[m + 1] = hsum2(a1h);
        TWb1l[m]     = hsum2(c0l);  TWb1h[m]     = hsum2(c0h);
        TWb1l[m + 1] = hsum2(c1l);  TWb1h[m + 1] = hsum2(c1h);
    }
    __syncwarp();   // s_v reused for E

    // ---- quad + E ----
    {
        float q0l = 0.f, q0h = 0.f, q1l = 0.f, q1h = 0.f;
#pragma unroll
        for (int i = 0; i < 4; i++) {
            q0l += fmaxf(A0l[i] + TWb0l[i] + blo, 0.0f);
            q0h += fmaxf(A0h[i] + TWb0h[i] + bhi, 0.0f);
            q1l += fmaxf(A1l[i] + TWb1l[i] + blo, 0.0f);
            q1h += fmaxf(A1h[i] + TWb1h[i] + bhi, 0.0f);
        }
        s_v[warp][0][0][t]      = fmaxf(q0l * 0.25f, 0.0f);
        s_v[warp][0][0][t + 32] = fmaxf(q0h * 0.25f, 0.0f);
        s_v[warp][1][0][t]      = fmaxf(q1l * 0.25f, 0.0f);
        s_v[warp][1][0][t + 32] = fmaxf(q1h * 0.25f, 0.0f);
    }
    __syncwarp();

    // ---- E2 = relu(hxwt + E@Wb + b), both nodes ----
    u64 e0l = 0ull, e0h = 0ull, e1l = 0ull, e1h = 0ull;
    {
        const u64* vA = (const u64*)s_v[warp][0][0];
        const u64* vB = (const u64*)s_v[warp][1][0];
#pragma unroll
        for (int k2 = 0; k2 < 32; k2++) {
            u64 a = vA[k2], b = vB[k2];
            ffma2(e0l, wlo[k2], a);  ffma2(e0h, whi[k2], a);
            ffma2(e1l, wlo[k2], b);  ffma2(e1h, whi[k2], b);
        }
    }
    float E20l = fmaxf(hx0l + hsum2(e0l) + blo, 0.0f);
    float E20h = fmaxf(hx0h + hsum2(e0h) + bhi, 0.0f);
    float E21l = fmaxf(hx1l + hsum2(e1l) + blo, 0.0f);
    float E21h = fmaxf(hx1h + hsum2(e1h) + bhi, 0.0f);

    // ---- readout head: y = E2 @ final_w + final_b, shfl butterflies ----
    float fwl0 = fw[t * 2 + 0],        fwl1 = fw[t * 2 + 1];
    float fwh0 = fw[(t + 32) * 2 + 0], fwh1 = fw[(t + 32) * 2 + 1];
    float p0 = E20l * fwl0 + E20h * fwh0;
    float p1 = E20l * fwl1 + E20h * fwh1;
    float q0 = E21l * fwl0 + E21h * fwh0;
    float q1 = E21l * fwl1 + E21h * fwh1;
#pragma unroll
    for (int off = 16; off > 0; off >>= 1) {
        p0 += __shfl_xor_sync(0xffffffffu, p0, off);
        p1 += __shfl_xor_sync(0xffffffffu, p1, off);
        q0 += __shfl_xor_sync(0xffffffffu, q0, off);
        q1 += __shfl_xor_sync(0xffffffffu, q1, off);
    }
    if (t == 0) {
        float2 oA = {p0 + fb[0], p1 + fb[1]};
        float2 oB = {q0 + fb[0], q1 + fb[1]};
        *(float2*)(out + l0 * 2) = oA;
        *(float2*)(out + l1 * 2) = oB;
    }
}

// ---------------------------------------------------------------------------
// kernel_launch: graph-capturable, allocation-free.
// Inputs: X, neighbors, h1_w, h1_b, g1_w, g1_b, final_w, final_b
// ---------------------------------------------------------------------------
extern "C" void kernel_launch(void* const* d_in, const int* in_sizes, int n_in,
                              void* d_out, int out_size)
{
    const float* X    = (const float*)d_in[0];
    const int*   nbr  = (const int*)  d_in[1];
    const float* h1w  = (const float*)d_in[2];
    const float* h1b  = (const float*)d_in[3];
    const float* g1w  = (const float*)d_in[4];
    const float* g1b  = (const float*)d_in[5];
    const float* fw   = (const float*)d_in[6];
    const float* fb   = (const float*)d_in[7];
    float* out = (float*)d_out;

    (void)in_sizes; (void)n_in; (void)out_size;

    prep_kernel<<<592, 256>>>(X, h1w, h1b, g1w);
    ggcn_main_kernel<<<L_NODES / 16, 256>>>(nbr, g1w, g1b, fw, fb, out);
}